// round 1
// baseline (speedup 1.0000x reference)
#include <cuda_runtime.h>
#include <math.h>

// Problem constants
#define BSZ 2
#define SSZ 1024
#define DSZ 1024
#define HN 16
#define DK 64
#define DFF 2048
#define LN_LAYERS 4

// Scratch (device globals: allocation-free)
__device__ float g_q[BSZ * SSZ * DSZ];
__device__ float g_k[BSZ * SSZ * DSZ];
__device__ float g_v[BSZ * SSZ * DSZ];
__device__ float g_o[BSZ * SSZ * DSZ];
__device__ float g_x[BSZ * SSZ * DSZ];
__device__ float g_h[BSZ * SSZ * DFF];

__device__ __forceinline__ float gelu_f(float x) {
    float x3 = x * x * x;
    float t  = tanhf(0.7978845608028654f * (x + 0.044715f * x3));
    return 0.5f * x * (1.0f + t);
}

// ---------------------------------------------------------------------------
// Generic tiled SGEMM: C[M,N] = A[M,K] @ B[K,N]  (+optional bias / bias+gelu)
// 64x64 tile, BK=16, 256 threads, 4x4 micro-tile per thread.
// mode: 0 = none, 1 = +bias, 2 = gelu(+bias)
// ---------------------------------------------------------------------------
__global__ void sgemm_kernel(const float* __restrict__ A,
                             const float* __restrict__ Bm,
                             float* __restrict__ C,
                             int M, int N, int K,
                             const float* __restrict__ bias, int mode) {
    __shared__ float As[64][17];
    __shared__ float Bs[16][65];

    int tid = threadIdx.x;
    int tx = tid & 15, ty = tid >> 4;
    int row0 = blockIdx.y * 64;
    int col0 = blockIdx.x * 64;

    float acc[4][4] = {};

    for (int k0 = 0; k0 < K; k0 += 16) {
#pragma unroll
        for (int i = 0; i < 4; i++) {
            int idx = tid + i * 256;
            int r = idx >> 4, c = idx & 15;
            As[r][c] = A[(size_t)(row0 + r) * K + k0 + c];
        }
#pragma unroll
        for (int i = 0; i < 4; i++) {
            int idx = tid + i * 256;
            int r = idx >> 6, c = idx & 63;
            Bs[r][c] = Bm[(size_t)(k0 + r) * N + col0 + c];
        }
        __syncthreads();
#pragma unroll
        for (int kk = 0; kk < 16; kk++) {
            float a[4], b[4];
#pragma unroll
            for (int i = 0; i < 4; i++) a[i] = As[ty * 4 + i][kk];
#pragma unroll
            for (int j = 0; j < 4; j++) b[j] = Bs[kk][tx * 4 + j];
#pragma unroll
            for (int i = 0; i < 4; i++)
#pragma unroll
                for (int j = 0; j < 4; j++) acc[i][j] += a[i] * b[j];
        }
        __syncthreads();
    }

#pragma unroll
    for (int i = 0; i < 4; i++) {
        int r = row0 + ty * 4 + i;
#pragma unroll
        for (int j = 0; j < 4; j++) {
            int c = col0 + tx * 4 + j;
            float v = acc[i][j];
            if (mode >= 1) v += bias[c];
            if (mode == 2) v = gelu_f(v);
            C[(size_t)r * N + c] = v;
        }
    }
}

// ---------------------------------------------------------------------------
// Attention scores: s[b,h,q,k] = scale * (Q_bh @ K_bh^T) + bias, masked.
// Q/K layout: [B, S, H*DK] row-major (head h slice at column h*DK).
// grid: (S/64, S/64, B*H), 256 threads.
// ---------------------------------------------------------------------------
__global__ void scores_kernel(const float* __restrict__ q,
                              const float* __restrict__ k,
                              const float* __restrict__ bias,
                              const int* __restrict__ mask,
                              float* __restrict__ sout) {
    __shared__ float Qs[64][17];
    __shared__ float Ks[64][17];

    int tid = threadIdx.x;
    int tx = tid & 15, ty = tid >> 4;
    int bh = blockIdx.z;
    int b = bh / HN, h = bh % HN;
    int k0 = blockIdx.x * 64;
    int q0 = blockIdx.y * 64;

    const size_t base = (size_t)b * SSZ * DSZ + (size_t)h * DK;
    float acc[4][4] = {};

    for (int d0 = 0; d0 < DK; d0 += 16) {
#pragma unroll
        for (int i = 0; i < 4; i++) {
            int idx = tid + i * 256;
            int r = idx >> 4, c = idx & 15;
            Qs[r][c] = q[base + (size_t)(q0 + r) * DSZ + d0 + c];
            Ks[r][c] = k[base + (size_t)(k0 + r) * DSZ + d0 + c];
        }
        __syncthreads();
#pragma unroll
        for (int kk = 0; kk < 16; kk++) {
            float a[4], bb[4];
#pragma unroll
            for (int i = 0; i < 4; i++) a[i] = Qs[ty * 4 + i][kk];
#pragma unroll
            for (int j = 0; j < 4; j++) bb[j] = Ks[tx * 4 + j][kk];
#pragma unroll
            for (int i = 0; i < 4; i++)
#pragma unroll
                for (int j = 0; j < 4; j++) acc[i][j] += a[i] * bb[j];
        }
        __syncthreads();
    }

    const float scale = 0.125f;  // 1/sqrt(64)
#pragma unroll
    for (int i = 0; i < 4; i++) {
        int qq = q0 + ty * 4 + i;
        size_t rowbase = (((size_t)b * HN + h) * SSZ + qq) * SSZ;
#pragma unroll
        for (int j = 0; j < 4; j++) {
            int kc = k0 + tx * 4 + j;
            float s = acc[i][j] * scale + bias[rowbase + kc];
            if (mask[b * SSZ + kc] == 0) s = -9e15f;
            sout[rowbase + kc] = s;
        }
    }
}

// ---------------------------------------------------------------------------
// Row softmax, in-place. One block per row (B*H*S rows), 256 threads.
// ---------------------------------------------------------------------------
__global__ void softmax_kernel(float* __restrict__ s) {
    __shared__ float sh[32];
    size_t row = blockIdx.x;
    float* p = s + row * SSZ;
    int tid = threadIdx.x;
    int lane = tid & 31, w = tid >> 5;

    float v[4];
    float mx = -INFINITY;
#pragma unroll
    for (int i = 0; i < 4; i++) {
        v[i] = p[tid + i * 256];
        mx = fmaxf(mx, v[i]);
    }
#pragma unroll
    for (int o = 16; o; o >>= 1) mx = fmaxf(mx, __shfl_xor_sync(0xffffffffu, mx, o));
    if (lane == 0) sh[w] = mx;
    __syncthreads();
    float m2 = (lane < 8) ? sh[lane] : -INFINITY;
#pragma unroll
    for (int o = 4; o; o >>= 1) m2 = fmaxf(m2, __shfl_xor_sync(0xffffffffu, m2, o));
    mx = __shfl_sync(0xffffffffu, m2, 0);

    float sum = 0.0f;
#pragma unroll
    for (int i = 0; i < 4; i++) {
        v[i] = __expf(v[i] - mx);
        sum += v[i];
    }
#pragma unroll
    for (int o = 16; o; o >>= 1) sum += __shfl_xor_sync(0xffffffffu, sum, o);
    __syncthreads();
    if (lane == 0) sh[w] = sum;
    __syncthreads();
    float s2 = (lane < 8) ? sh[lane] : 0.0f;
#pragma unroll
    for (int o = 4; o; o >>= 1) s2 += __shfl_xor_sync(0xffffffffu, s2, o);
    float inv = 1.0f / __shfl_sync(0xffffffffu, s2, 0);

#pragma unroll
    for (int i = 0; i < 4; i++) p[tid + i * 256] = v[i] * inv;
}

// ---------------------------------------------------------------------------
// PV: O_bh[S, DK] = P_bh[S, S] @ V_bh[S, DK]; O stored as [B,S,H*DK].
// grid: (1, S/64, B*H), 256 threads, 64(q) x 64(d) output tile.
// ---------------------------------------------------------------------------
__global__ void pv_kernel(const float* __restrict__ p,
                          const float* __restrict__ v,
                          float* __restrict__ o) {
    __shared__ float Ps[64][17];
    __shared__ float Vs[16][65];

    int tid = threadIdx.x;
    int tx = tid & 15, ty = tid >> 4;
    int bh = blockIdx.z;
    int b = bh / HN, h = bh % HN;
    int q0 = blockIdx.y * 64;

    const size_t pbase = ((size_t)b * HN + h) * SSZ * SSZ;
    const size_t vbase = (size_t)b * SSZ * DSZ + (size_t)h * DK;

    float acc[4][4] = {};
    for (int k0 = 0; k0 < SSZ; k0 += 16) {
#pragma unroll
        for (int i = 0; i < 4; i++) {
            int idx = tid + i * 256;
            int r = idx >> 4, c = idx & 15;
            Ps[r][c] = p[pbase + (size_t)(q0 + r) * SSZ + k0 + c];
        }
#pragma unroll
        for (int i = 0; i < 4; i++) {
            int idx = tid + i * 256;
            int r = idx >> 6, c = idx & 63;
            Vs[r][c] = v[vbase + (size_t)(k0 + r) * DSZ + c];
        }
        __syncthreads();
#pragma unroll
        for (int kk = 0; kk < 16; kk++) {
            float a[4], bb[4];
#pragma unroll
            for (int i = 0; i < 4; i++) a[i] = Ps[ty * 4 + i][kk];
#pragma unroll
            for (int j = 0; j < 4; j++) bb[j] = Vs[kk][tx * 4 + j];
#pragma unroll
            for (int i = 0; i < 4; i++)
#pragma unroll
                for (int j = 0; j < 4; j++) acc[i][j] += a[i] * bb[j];
        }
        __syncthreads();
    }

#pragma unroll
    for (int i = 0; i < 4; i++) {
        size_t obase = vbase + (size_t)(q0 + ty * 4 + i) * DSZ;
#pragma unroll
        for (int j = 0; j < 4; j++) o[obase + tx * 4 + j] = acc[i][j];
    }
}

// ---------------------------------------------------------------------------
// Fused residual add + LayerNorm. One block per row (B*S rows), 256 threads.
// out = LN(resid + add) * g + b    (out may alias resid: regs-first, safe)
// ---------------------------------------------------------------------------
__global__ void add_ln_kernel(const float* __restrict__ resid,
                              const float* __restrict__ add,
                              const float* __restrict__ g,
                              const float* __restrict__ bta,
                              float* __restrict__ out) {
    __shared__ float sh[32];
    size_t row = blockIdx.x;
    int tid = threadIdx.x;
    int lane = tid & 31, w = tid >> 5;
    const size_t base = row * DSZ;

    float v[4];
    float sum = 0.0f;
#pragma unroll
    for (int i = 0; i < 4; i++) {
        int c = tid + i * 256;
        v[i] = resid[base + c] + add[base + c];
        sum += v[i];
    }
#pragma unroll
    for (int o = 16; o; o >>= 1) sum += __shfl_xor_sync(0xffffffffu, sum, o);
    if (lane == 0) sh[w] = sum;
    __syncthreads();
    float t = (lane < 8) ? sh[lane] : 0.0f;
#pragma unroll
    for (int o = 4; o; o >>= 1) t += __shfl_xor_sync(0xffffffffu, t, o);
    float mu = __shfl_sync(0xffffffffu, t, 0) * (1.0f / DSZ);

    float s2 = 0.0f;
#pragma unroll
    for (int i = 0; i < 4; i++) {
        float d = v[i] - mu;
        s2 += d * d;
    }
#pragma unroll
    for (int o = 16; o; o >>= 1) s2 += __shfl_xor_sync(0xffffffffu, s2, o);
    __syncthreads();
    if (lane == 0) sh[w] = s2;
    __syncthreads();
    float t2 = (lane < 8) ? sh[lane] : 0.0f;
#pragma unroll
    for (int o = 4; o; o >>= 1) t2 += __shfl_xor_sync(0xffffffffu, t2, o);
    float var = __shfl_sync(0xffffffffu, t2, 0) * (1.0f / DSZ);
    float rstd = rsqrtf(var + 1e-6f);

#pragma unroll
    for (int i = 0; i < 4; i++) {
        int c = tid + i * 256;
        out[base + c] = (v[i] - mu) * rstd * g[c] + bta[c];
    }
}

// ---------------------------------------------------------------------------
// Host-side orchestration
// ---------------------------------------------------------------------------
extern "C" void kernel_launch(void* const* d_in, const int* in_sizes, int n_in,
                              void* d_out, int out_size) {
    (void)in_sizes; (void)n_in; (void)out_size;

    const float* x_in  = (const float*)d_in[0];
    const int*   mask  = (const int*)  d_in[1];
    const float* bias  = (const float*)d_in[2];
    const float* Wq    = (const float*)d_in[3];
    const float* Wk    = (const float*)d_in[4];
    const float* Wv    = (const float*)d_in[5];
    const float* ln1g  = (const float*)d_in[6];
    const float* ln1b  = (const float*)d_in[7];
    const float* W1    = (const float*)d_in[8];
    const float* b1    = (const float*)d_in[9];
    const float* W2    = (const float*)d_in[10];
    const float* b2    = (const float*)d_in[11];
    const float* ln2g  = (const float*)d_in[12];
    const float* ln2b  = (const float*)d_in[13];
    float* out = (float*)d_out;

    float *q, *k, *v, *o, *x, *hbuf;
    cudaGetSymbolAddress((void**)&q, g_q);
    cudaGetSymbolAddress((void**)&k, g_k);
    cudaGetSymbolAddress((void**)&v, g_v);
    cudaGetSymbolAddress((void**)&o, g_o);
    cudaGetSymbolAddress((void**)&x, g_x);
    cudaGetSymbolAddress((void**)&hbuf, g_h);

    const int M = BSZ * SSZ;                       // 2048
    const size_t SCORES_L = (size_t)BSZ * HN * SSZ * SSZ;  // per-layer score count

    cudaMemcpyAsync(x, x_in, sizeof(float) * M * DSZ, cudaMemcpyDeviceToDevice);

    dim3 thr(256);
    for (int n = 0; n < LN_LAYERS; n++) {
        const float* wq = Wq + (size_t)n * DSZ * DSZ;
        const float* wk = Wk + (size_t)n * DSZ * DSZ;
        const float* wv = Wv + (size_t)n * DSZ * DSZ;
        float* sl = out + (size_t)n * SCORES_L;

        sgemm_kernel<<<dim3(DSZ / 64, M / 64), thr>>>(x, wq, q, M, DSZ, DSZ, nullptr, 0);
        sgemm_kernel<<<dim3(DSZ / 64, M / 64), thr>>>(x, wk, k, M, DSZ, DSZ, nullptr, 0);
        sgemm_kernel<<<dim3(DSZ / 64, M / 64), thr>>>(x, wv, v, M, DSZ, DSZ, nullptr, 0);

        scores_kernel<<<dim3(SSZ / 64, SSZ / 64, BSZ * HN), thr>>>(q, k, bias, mask, sl);
        softmax_kernel<<<BSZ * HN * SSZ, thr>>>(sl);
        pv_kernel<<<dim3(1, SSZ / 64, BSZ * HN), thr>>>(sl, v, o);

        add_ln_kernel<<<M, thr>>>(x, o, ln1g + n * DSZ, ln1b + n * DSZ, x);

        sgemm_kernel<<<dim3(DFF / 64, M / 64), thr>>>(x, W1 + (size_t)n * DSZ * DFF, hbuf,
                                                      M, DFF, DSZ, b1 + (size_t)n * DFF, 2);
        sgemm_kernel<<<dim3(DSZ / 64, M / 64), thr>>>(hbuf, W2 + (size_t)n * DFF * DSZ, o,
                                                      M, DSZ, DFF, b2 + (size_t)n * DSZ, 1);

        add_ln_kernel<<<M, thr>>>(x, o, ln2g + n * DSZ, ln2b + n * DSZ, x);
    }

    cudaMemcpyAsync(out + (size_t)LN_LAYERS * SCORES_L, x,
                    sizeof(float) * M * DSZ, cudaMemcpyDeviceToDevice);
}

// round 2
// speedup vs baseline: 2.8042x; 2.8042x over previous
#include <cuda_runtime.h>
#include <math.h>
#include <stdint.h>

// Problem constants
#define BSZ 2
#define SSZ 1024
#define DSZ 1024
#define HN 16
#define DK 64
#define DFF 2048
#define LN_LAYERS 4

// Scratch (device globals: allocation-free)
__device__ float g_q[BSZ * SSZ * DSZ];
__device__ float g_k[BSZ * SSZ * DSZ];
__device__ float g_v[BSZ * SSZ * DSZ];
__device__ float g_o[BSZ * SSZ * DSZ];
__device__ float g_x[BSZ * SSZ * DSZ];
__device__ float g_h[BSZ * SSZ * DFF];

__device__ __forceinline__ float gelu_f(float x) {
    float x3 = x * x * x;
    float t  = tanhf(0.7978845608028654f * (x + 0.044715f * x3));
    return 0.5f * x * (1.0f + t);
}

__device__ __forceinline__ float tf32r(float x) {
    uint32_t u;
    asm("cvt.rna.tf32.f32 %0, %1;" : "=r"(u) : "f"(x));
    return __uint_as_float(u);
}

__device__ __forceinline__ void mma_tf32(float* d, const uint32_t* a, const uint32_t* b) {
    asm volatile(
        "mma.sync.aligned.m16n8k8.row.col.f32.tf32.tf32.f32 "
        "{%0,%1,%2,%3}, {%4,%5,%6,%7}, {%8,%9}, {%0,%1,%2,%3};\n"
        : "+f"(d[0]), "+f"(d[1]), "+f"(d[2]), "+f"(d[3])
        : "r"(a[0]), "r"(a[1]), "r"(a[2]), "r"(a[3]), "r"(b[0]), "r"(b[1]));
}

// ---------------------------------------------------------------------------
// Batched tf32 tensor-core GEMM: C[z][M,N] = A[z][M,K] @ B[z][K,N]
// Block tile 64 x BN, BK=16, 256 threads = 8 warps (2 m x 4 n).
// Per-z operand offset = (z/16)*sb + (z%16)*sh  (covers linear & [b,h] strides)
// TRANSB: B memory holds [N,K] row-major (used for Q @ K^T).
// mode: 0 plain, 1 +bias1d[n], 2 gelu(+bias1d[n]),
//       3 scores: scale*acc + bias3 (same layout/offsets as C) + key mask.
// ---------------------------------------------------------------------------
template<int BN, bool TRANSB>
__global__ __launch_bounds__(256)
void mma_gemm(const float* __restrict__ A, const float* __restrict__ B,
              float* __restrict__ C,
              int M, int N, int K, int lda, int ldb, int ldc,
              long long asb, long long ash,
              long long bsb, long long bsh,
              long long csb, long long csh,
              const float* __restrict__ bias, const int* __restrict__ mask,
              int mode, float scale) {
    constexpr int BM  = 64, BK = 16;
    constexpr int AST = 20;                    // As row stride (conflict-free frags)
    constexpr int BST = TRANSB ? BN + 4 : BN + 8;
    constexpr int WN  = BN / 4;                // 32 or 16 cols per warp
    constexpr int NT  = WN / 8;                // 4 or 2 n-tiles per warp
    constexpr int BITER = (BN * BK / 4) / 256; // B-tile float4s per thread

    __shared__ float As[BM][AST];
    __shared__ float Bs[BK][BST];

    const int tid  = threadIdx.x;
    const int lane = tid & 31;
    const int warp = tid >> 5;
    const int wm   = warp & 1;   // 0..1  (32 rows each)
    const int wn   = warp >> 1;  // 0..3  (WN cols each)

    const int z  = blockIdx.z;
    const int zb = z >> 4, zh = z & 15;
    A += (long long)zb * asb + (long long)zh * ash;
    B += (long long)zb * bsb + (long long)zh * bsh;
    C += (long long)zb * csb + (long long)zh * csh;
    const float* bias3 = bias ? (bias + (long long)zb * csb + (long long)zh * csh) : bias;

    const int m0 = blockIdx.y * BM;
    const int n0 = blockIdx.x * BN;

    float acc[2][NT][4];
#pragma unroll
    for (int i = 0; i < 2; i++)
#pragma unroll
        for (int j = 0; j < NT; j++)
#pragma unroll
            for (int l = 0; l < 4; l++) acc[i][j][l] = 0.0f;

    for (int k0 = 0; k0 < K; k0 += BK) {
        // --- A tile: 64 x 16 -> As[m][k] (tf32-rounded) ---
        {
            const int r  = tid >> 2;
            const int c4 = (tid & 3) << 2;
            const float4 v = *(const float4*)&A[(size_t)(m0 + r) * lda + k0 + c4];
            float4 t;
            t.x = tf32r(v.x); t.y = tf32r(v.y); t.z = tf32r(v.z); t.w = tf32r(v.w);
            *(float4*)&As[r][c4] = t;
        }
        // --- B tile -> Bs[k][n] (tf32-rounded) ---
        if (TRANSB) {
#pragma unroll
            for (int i = 0; i < BITER; i++) {
                const int idx = tid + i * 256;
                const int r   = idx >> 2;          // n index
                const int c4  = (idx & 3) << 2;    // k index
                const float4 v = *(const float4*)&B[(size_t)(n0 + r) * ldb + k0 + c4];
                Bs[c4 + 0][r] = tf32r(v.x);
                Bs[c4 + 1][r] = tf32r(v.y);
                Bs[c4 + 2][r] = tf32r(v.z);
                Bs[c4 + 3][r] = tf32r(v.w);
            }
        } else {
#pragma unroll
            for (int i = 0; i < BITER; i++) {
                const int idx = tid + i * 256;
                const int r   = idx / (BN / 4);          // k index
                const int c4  = (idx % (BN / 4)) << 2;   // n index
                const float4 v = *(const float4*)&B[(size_t)(k0 + r) * ldb + n0 + c4];
                float4 t;
                t.x = tf32r(v.x); t.y = tf32r(v.y); t.z = tf32r(v.z); t.w = tf32r(v.w);
                *(float4*)&Bs[r][c4] = t;
            }
        }
        __syncthreads();

#pragma unroll
        for (int ks = 0; ks < 2; ks++) {
            const int kk = ks * 8;
            const int ak = kk + (lane & 3);
            const int am = wm * 32 + (lane >> 2);
            uint32_t a[2][4];
#pragma unroll
            for (int mt = 0; mt < 2; mt++) {
                a[mt][0] = __float_as_uint(As[am + mt * 16    ][ak    ]);
                a[mt][1] = __float_as_uint(As[am + mt * 16 + 8][ak    ]);
                a[mt][2] = __float_as_uint(As[am + mt * 16    ][ak + 4]);
                a[mt][3] = __float_as_uint(As[am + mt * 16 + 8][ak + 4]);
            }
            const int bn = wn * WN + (lane >> 2);
            uint32_t b[NT][2];
#pragma unroll
            for (int nt = 0; nt < NT; nt++) {
                b[nt][0] = __float_as_uint(Bs[ak    ][bn + nt * 8]);
                b[nt][1] = __float_as_uint(Bs[ak + 4][bn + nt * 8]);
            }
#pragma unroll
            for (int mt = 0; mt < 2; mt++)
#pragma unroll
                for (int nt = 0; nt < NT; nt++)
                    mma_tf32(acc[mt][nt], a[mt], b[nt]);
        }
        __syncthreads();
    }

    // --- Epilogue ---
#pragma unroll
    for (int mt = 0; mt < 2; mt++) {
        const int r0 = m0 + wm * 32 + mt * 16 + (lane >> 2);
#pragma unroll
        for (int nt = 0; nt < NT; nt++) {
            const int c = n0 + wn * WN + nt * 8 + ((lane & 3) << 1);
            float v0 = acc[mt][nt][0], v1 = acc[mt][nt][1];
            float v2 = acc[mt][nt][2], v3 = acc[mt][nt][3];
            if (mode == 1) {
                float b0 = bias[c], b1 = bias[c + 1];
                v0 += b0; v1 += b1; v2 += b0; v3 += b1;
            } else if (mode == 2) {
                float b0 = bias[c], b1 = bias[c + 1];
                v0 = gelu_f(v0 + b0); v1 = gelu_f(v1 + b1);
                v2 = gelu_f(v2 + b0); v3 = gelu_f(v3 + b1);
            } else if (mode == 3) {
                const size_t i0 = (size_t)r0 * ldc + c;
                const size_t i1 = (size_t)(r0 + 8) * ldc + c;
                v0 = v0 * scale + bias3[i0];
                v1 = v1 * scale + bias3[i0 + 1];
                v2 = v2 * scale + bias3[i1];
                v3 = v3 * scale + bias3[i1 + 1];
                if (mask[(z >> 4) * N + c] == 0)     { v0 = -9e15f; v2 = -9e15f; }
                if (mask[(z >> 4) * N + c + 1] == 0) { v1 = -9e15f; v3 = -9e15f; }
            }
            *(float2*)&C[(size_t)r0 * ldc + c]       = make_float2(v0, v1);
            *(float2*)&C[(size_t)(r0 + 8) * ldc + c] = make_float2(v2, v3);
        }
    }
}

// ---------------------------------------------------------------------------
// Row softmax, in-place. One block per row (B*H*S rows), 256 threads.
// ---------------------------------------------------------------------------
__global__ void softmax_kernel(float* __restrict__ s) {
    __shared__ float sh[32];
    size_t row = blockIdx.x;
    float* p = s + row * SSZ;
    int tid = threadIdx.x;
    int lane = tid & 31, w = tid >> 5;

    float v[4];
    float mx = -INFINITY;
#pragma unroll
    for (int i = 0; i < 4; i++) {
        v[i] = p[tid + i * 256];
        mx = fmaxf(mx, v[i]);
    }
#pragma unroll
    for (int o = 16; o; o >>= 1) mx = fmaxf(mx, __shfl_xor_sync(0xffffffffu, mx, o));
    if (lane == 0) sh[w] = mx;
    __syncthreads();
    float m2 = (lane < 8) ? sh[lane] : -INFINITY;
#pragma unroll
    for (int o = 4; o; o >>= 1) m2 = fmaxf(m2, __shfl_xor_sync(0xffffffffu, m2, o));
    mx = __shfl_sync(0xffffffffu, m2, 0);

    float sum = 0.0f;
#pragma unroll
    for (int i = 0; i < 4; i++) {
        v[i] = __expf(v[i] - mx);
        sum += v[i];
    }
#pragma unroll
    for (int o = 16; o; o >>= 1) sum += __shfl_xor_sync(0xffffffffu, sum, o);
    __syncthreads();
    if (lane == 0) sh[w] = sum;
    __syncthreads();
    float s2 = (lane < 8) ? sh[lane] : 0.0f;
#pragma unroll
    for (int o = 4; o; o >>= 1) s2 += __shfl_xor_sync(0xffffffffu, s2, o);
    float inv = 1.0f / __shfl_sync(0xffffffffu, s2, 0);

#pragma unroll
    for (int i = 0; i < 4; i++) p[tid + i * 256] = v[i] * inv;
}

// ---------------------------------------------------------------------------
// Fused residual add + LayerNorm. One block per row (B*S rows), 256 threads.
// ---------------------------------------------------------------------------
__global__ void add_ln_kernel(const float* __restrict__ resid,
                              const float* __restrict__ add,
                              const float* __restrict__ g,
                              const float* __restrict__ bta,
                              float* __restrict__ out) {
    __shared__ float sh[32];
    size_t row = blockIdx.x;
    int tid = threadIdx.x;
    int lane = tid & 31, w = tid >> 5;
    const size_t base = row * DSZ;

    float v[4];
    float sum = 0.0f;
#pragma unroll
    for (int i = 0; i < 4; i++) {
        int c = tid + i * 256;
        v[i] = resid[base + c] + add[base + c];
        sum += v[i];
    }
#pragma unroll
    for (int o = 16; o; o >>= 1) sum += __shfl_xor_sync(0xffffffffu, sum, o);
    if (lane == 0) sh[w] = sum;
    __syncthreads();
    float t = (lane < 8) ? sh[lane] : 0.0f;
#pragma unroll
    for (int o = 4; o; o >>= 1) t += __shfl_xor_sync(0xffffffffu, t, o);
    float mu = __shfl_sync(0xffffffffu, t, 0) * (1.0f / DSZ);

    float s2 = 0.0f;
#pragma unroll
    for (int i = 0; i < 4; i++) {
        float d = v[i] - mu;
        s2 += d * d;
    }
#pragma unroll
    for (int o = 16; o; o >>= 1) s2 += __shfl_xor_sync(0xffffffffu, s2, o);
    __syncthreads();
    if (lane == 0) sh[w] = s2;
    __syncthreads();
    float t2 = (lane < 8) ? sh[lane] : 0.0f;
#pragma unroll
    for (int o = 4; o; o >>= 1) t2 += __shfl_xor_sync(0xffffffffu, t2, o);
    float var = __shfl_sync(0xffffffffu, t2, 0) * (1.0f / DSZ);
    float rstd = rsqrtf(var + 1e-6f);

#pragma unroll
    for (int i = 0; i < 4; i++) {
        int c = tid + i * 256;
        out[base + c] = (v[i] - mu) * rstd * g[c] + bta[c];
    }
}

// ---------------------------------------------------------------------------
// Host-side orchestration
// ---------------------------------------------------------------------------
extern "C" void kernel_launch(void* const* d_in, const int* in_sizes, int n_in,
                              void* d_out, int out_size) {
    (void)in_sizes; (void)n_in; (void)out_size;

    const float* x_in  = (const float*)d_in[0];
    const int*   mask  = (const int*)  d_in[1];
    const float* bias  = (const float*)d_in[2];
    const float* Wq    = (const float*)d_in[3];
    const float* Wk    = (const float*)d_in[4];
    const float* Wv    = (const float*)d_in[5];
    const float* ln1g  = (const float*)d_in[6];
    const float* ln1b  = (const float*)d_in[7];
    const float* W1    = (const float*)d_in[8];
    const float* b1    = (const float*)d_in[9];
    const float* W2    = (const float*)d_in[10];
    const float* b2    = (const float*)d_in[11];
    const float* ln2g  = (const float*)d_in[12];
    const float* ln2b  = (const float*)d_in[13];
    float* out = (float*)d_out;

    float *q, *k, *v, *o, *x, *hbuf;
    cudaGetSymbolAddress((void**)&q, g_q);
    cudaGetSymbolAddress((void**)&k, g_k);
    cudaGetSymbolAddress((void**)&v, g_v);
    cudaGetSymbolAddress((void**)&o, g_o);
    cudaGetSymbolAddress((void**)&x, g_x);
    cudaGetSymbolAddress((void**)&hbuf, g_h);

    const int M = BSZ * SSZ;                               // 2048
    const long long SL = (long long)SSZ * SSZ;             // per-head score elems
    const long long SCORES_L = (long long)BSZ * HN * SL;   // per-layer score elems
    const long long SD = (long long)SSZ * DSZ;

    cudaMemcpyAsync(x, x_in, sizeof(float) * (size_t)M * DSZ, cudaMemcpyDeviceToDevice);

    dim3 thr(256);
    for (int n = 0; n < LN_LAYERS; n++) {
        const float* wq = Wq + (size_t)n * DSZ * DSZ;
        const float* wk = Wk + (size_t)n * DSZ * DSZ;
        const float* wv = Wv + (size_t)n * DSZ * DSZ;
        float* sl = out + (size_t)n * SCORES_L;

        // QKV projections: [2048,1024] = [2048,1024] @ [1024,1024]
        mma_gemm<128, false><<<dim3(DSZ / 128, M / 64, 1), thr>>>(
            x, wq, q, M, DSZ, DSZ, DSZ, DSZ, DSZ,
            0, 0, 0, 0, 0, 0, nullptr, nullptr, 0, 0.0f);
        mma_gemm<128, false><<<dim3(DSZ / 128, M / 64, 1), thr>>>(
            x, wk, k, M, DSZ, DSZ, DSZ, DSZ, DSZ,
            0, 0, 0, 0, 0, 0, nullptr, nullptr, 0, 0.0f);
        mma_gemm<128, false><<<dim3(DSZ / 128, M / 64, 1), thr>>>(
            x, wv, v, M, DSZ, DSZ, DSZ, DSZ, DSZ,
            0, 0, 0, 0, 0, 0, nullptr, nullptr, 0, 0.0f);

        // Scores: per (b,h): S x S = Q_bh[S,64] @ K_bh[S,64]^T, fused scale+bias+mask
        mma_gemm<128, true><<<dim3(SSZ / 128, SSZ / 64, BSZ * HN), thr>>>(
            q, k, sl, SSZ, SSZ, DK, DSZ, DSZ, SSZ,
            SD, (long long)DK,          // A (q): per-b, per-h
            SD, (long long)DK,          // B (k)
            (long long)HN * SL, SL,     // C (scores): linear z stride S*S
            bias, mask, 3, 0.125f);

        softmax_kernel<<<BSZ * HN * SSZ, thr>>>(sl);

        // PV: per (b,h): [S,64] = P[S,S] @ V_bh[S,64]
        mma_gemm<64, false><<<dim3(1, SSZ / 64, BSZ * HN), thr>>>(
            sl, v, o, SSZ, DK, SSZ, SSZ, DSZ, DSZ,
            (long long)HN * SL, SL,     // A (p): linear z stride S*S
            SD, (long long)DK,          // B (v)
            SD, (long long)DK,          // C (o)
            nullptr, nullptr, 0, 0.0f);

        add_ln_kernel<<<M, thr>>>(x, o, ln1g + n * DSZ, ln1b + n * DSZ, x);

        // FFN1: [2048,2048] = x @ W1 (+b1, gelu)
        mma_gemm<128, false><<<dim3(DFF / 128, M / 64, 1), thr>>>(
            x, W1 + (size_t)n * DSZ * DFF, hbuf, M, DFF, DSZ, DSZ, DFF, DFF,
            0, 0, 0, 0, 0, 0, b1 + (size_t)n * DFF, nullptr, 2, 0.0f);
        // FFN2: [2048,1024] = h @ W2 (+b2)
        mma_gemm<128, false><<<dim3(DSZ / 128, M / 64, 1), thr>>>(
            hbuf, W2 + (size_t)n * DFF * DSZ, o, M, DSZ, DFF, DFF, DSZ, DSZ,
            0, 0, 0, 0, 0, 0, b2 + (size_t)n * DSZ, nullptr, 1, 0.0f);

        add_ln_kernel<<<M, thr>>>(x, o, ln2g + n * DSZ, ln2b + n * DSZ, x);
    }

    cudaMemcpyAsync(out + (size_t)LN_LAYERS * SCORES_L, x,
                    sizeof(float) * (size_t)M * DSZ, cudaMemcpyDeviceToDevice);
}

// round 3
// speedup vs baseline: 3.5086x; 1.2512x over previous
#include <cuda_runtime.h>
#include <math.h>
#include <stdint.h>

// Problem constants
#define BSZ 2
#define SSZ 1024
#define DSZ 1024
#define HN 16
#define DK 64
#define DFF 2048
#define LN_LAYERS 4

// Scratch (device globals: allocation-free)
__device__ float g_q[BSZ * SSZ * DSZ];
__device__ float g_k[BSZ * SSZ * DSZ];
__device__ float g_v[BSZ * SSZ * DSZ];
__device__ float g_o[BSZ * SSZ * DSZ];
__device__ float g_x[BSZ * SSZ * DSZ];
__device__ float g_h[BSZ * SSZ * DFF];

__device__ __forceinline__ float gelu_f(float x) {
    float x3 = x * x * x;
    float t  = tanhf(0.7978845608028654f * (x + 0.044715f * x3));
    return 0.5f * x * (1.0f + t);
}

__device__ __forceinline__ float tf32r(float x) {
    uint32_t u;
    asm("cvt.rna.tf32.f32 %0, %1;" : "=r"(u) : "f"(x));
    return __uint_as_float(u);
}
__device__ __forceinline__ float4 tf32r4(float4 v) {
    float4 t;
    t.x = tf32r(v.x); t.y = tf32r(v.y); t.z = tf32r(v.z); t.w = tf32r(v.w);
    return t;
}

__device__ __forceinline__ void ldsm4(uint32_t& r0, uint32_t& r1, uint32_t& r2,
                                      uint32_t& r3, uint32_t addr) {
    asm volatile("ldmatrix.sync.aligned.m8n8.x4.shared.b16 {%0,%1,%2,%3}, [%4];\n"
                 : "=r"(r0), "=r"(r1), "=r"(r2), "=r"(r3) : "r"(addr));
}

__device__ __forceinline__ void mma_tf32(float* d, const uint32_t* a, const uint32_t* b) {
    asm volatile(
        "mma.sync.aligned.m16n8k8.row.col.f32.tf32.tf32.f32 "
        "{%0,%1,%2,%3}, {%4,%5,%6,%7}, {%8,%9}, {%0,%1,%2,%3};\n"
        : "+f"(d[0]), "+f"(d[1]), "+f"(d[2]), "+f"(d[3])
        : "r"(a[0]), "r"(a[1]), "r"(a[2]), "r"(a[3]), "r"(b[0]), "r"(b[1]));
}

// ---------------------------------------------------------------------------
// tf32 tensor-core GEMM, 128 x BN x 32 block tile, 256 threads = 8 warps (2x4).
// Warp tile 64 x (BN/4). Fragments fed via ldmatrix (A always; B when TRANSB).
// Smem swizzled conflict-free. Double-buffered via register staging.
// qkv!=0: blockIdx.z in {0,1,2} selects (B0,C0)/(B1,C1)/(B2,C2), no z offsets.
// else:   per-z operand offset = (z/16)*sb + (z%16)*sh.
// mode: 0 plain, 1 +bias[n], 2 gelu(+bias[n]),
//       3 scores: scale*acc + attn_bias (C-layout offsets) + key mask.
// ---------------------------------------------------------------------------
template<int BN, bool TRANSB>
__global__ void __launch_bounds__(256) mma_gemm(
    const float* __restrict__ A,
    const float* __restrict__ B0, const float* __restrict__ B1, const float* __restrict__ B2,
    float* __restrict__ C0, float* __restrict__ C1, float* __restrict__ C2,
    int lda, int ldb, int ldc, int K,
    long long asb, long long ash, long long bsb, long long bsh,
    long long csb, long long csh,
    const float* __restrict__ bias, const int* __restrict__ mask,
    int mode, float scale, int qkv)
{
    constexpr int BM = 128, BK = 32;
    constexpr int WNW = BN / 4;        // warp n-width: 32 (BN=128) or 16 (BN=64)
    constexpr int NT  = WNW / 8;       // n-tiles per warp: 4 or 2
    constexpr int NB4 = BN / 32;       // B float4 per thread per tile

    extern __shared__ float sm[];
    float* BsBuf = sm + 2 * BM * BK;
    const uint32_t smemBase = (uint32_t)__cvta_generic_to_shared(sm);

    const int tid = threadIdx.x, lane = tid & 31, warp = tid >> 5;
    const int wm = warp & 1, wn = warp >> 1;
    const int z = blockIdx.z;
    const int zb = z >> 4, zh = z & 15;

    const float* B = B0;
    float* C = C0;
    if (qkv) {
        if (z == 1) { B = B1; C = C1; }
        else if (z == 2) { B = B2; C = C2; }
    } else {
        A += (long long)zb * asb + (long long)zh * ash;
        B += (long long)zb * bsb + (long long)zh * bsh;
        C += (long long)zb * csb + (long long)zh * csh;
    }
    const float* bias3 = (mode == 3) ? (bias + (long long)zb * csb + (long long)zh * csh)
                                     : bias;

    const int m0 = blockIdx.y * BM;
    const int n0 = blockIdx.x * BN;

    // ---- staging pointers / store offsets ----
    const float* Aptr[4];
    int aSto[4];
#pragma unroll
    for (int i = 0; i < 4; i++) {
        int idx = tid + i * 256;
        int r = idx >> 3, cq = idx & 7;
        Aptr[i] = A + (size_t)(m0 + r) * lda + cq * 4;
        aSto[i] = r * BK + ((cq ^ (r & 7)) << 2);
    }
    const float* Bptr[NB4];
    int bSto[NB4];
#pragma unroll
    for (int i = 0; i < NB4; i++) {
        int idx = tid + i * 256;
        if (TRANSB) {
            int r = idx >> 3, cq = idx & 7;          // r = n row, k contiguous
            Bptr[i] = B + (size_t)(n0 + r) * ldb + cq * 4;
            bSto[i] = r * BK + ((cq ^ (r & 7)) << 2);
        } else {
            int kk = idx / (BN / 4), nq = idx % (BN / 4);
            Bptr[i] = B + (size_t)kk * ldb + n0 + nq * 4;
            bSto[i] = kk * BN + ((nq ^ ((kk & 3) << 1)) << 2);
        }
    }

    // ---- fragment addressing ----
    const int aXor = lane & 7, aHi = lane >> 4;
    const uint32_t aBase = smemBase + ((wm * 64 + (lane & 15)) * BK) * 4;
    const uint32_t bBaseT = smemBase + (2 * BM * BK + (wn * WNW + (lane & 15)) * BK) * 4;
    const int bk = lane & 3, bn = lane >> 2;
    int bWord[NT];
#pragma unroll
    for (int nt = 0; nt < NT; nt++) {
        int n_l = wn * WNW + nt * 8 + bn;
        bWord[nt] = (((n_l >> 2) ^ (bk << 1)) << 2) + (n_l & 3);
    }

    float acc[4][NT][4];
#pragma unroll
    for (int mt = 0; mt < 4; mt++)
#pragma unroll
        for (int nt = 0; nt < NT; nt++)
#pragma unroll
            for (int l = 0; l < 4; l++) acc[mt][nt][l] = 0.0f;

    float4 ar[4], br[NB4];

#define LDG_TILE(IT)                                                          \
    {                                                                         \
        const int koff = (IT) * BK;                                           \
        _Pragma("unroll")                                                     \
        for (int i = 0; i < 4; i++)                                           \
            ar[i] = *(const float4*)(Aptr[i] + koff);                         \
        _Pragma("unroll")                                                     \
        for (int i = 0; i < NB4; i++)                                         \
            br[i] = TRANSB ? *(const float4*)(Bptr[i] + koff)                 \
                           : *(const float4*)(Bptr[i] + (size_t)koff * ldb);  \
    }

#define STS_TILE(BUF)                                                         \
    {                                                                         \
        float* as = sm + (BUF) * BM * BK;                                     \
        float* bs = BsBuf + (BUF) * BN * BK;                                  \
        _Pragma("unroll")                                                     \
        for (int i = 0; i < 4; i++) *(float4*)&as[aSto[i]] = tf32r4(ar[i]);   \
        _Pragma("unroll")                                                     \
        for (int i = 0; i < NB4; i++) *(float4*)&bs[bSto[i]] = tf32r4(br[i]); \
    }

#define COMPUTE(BUF)                                                          \
    {                                                                         \
        _Pragma("unroll")                                                     \
        for (int ks = 0; ks < 4; ks++) {                                      \
            const uint32_t chunkx = (uint32_t)(((ks * 2 + aHi) ^ aXor) << 4); \
            uint32_t a[4][4];                                                 \
            const uint32_t ab = aBase + (BUF) * (BM * BK * 4) + chunkx;       \
            _Pragma("unroll")                                                 \
            for (int mt = 0; mt < 4; mt++)                                    \
                ldsm4(a[mt][0], a[mt][1], a[mt][2], a[mt][3],                 \
                      ab + mt * 16 * BK * 4);                                 \
            uint32_t b[NT][2];                                                \
            if (TRANSB) {                                                     \
                const uint32_t bb = bBaseT + (BUF) * (BN * BK * 4) + chunkx;  \
                _Pragma("unroll")                                             \
                for (int h = 0; h < NT / 2; h++) {                            \
                    uint32_t r0, r1, r2, r3;                                  \
                    ldsm4(r0, r1, r2, r3, bb + h * 16 * BK * 4);              \
                    b[2*h][0] = r0; b[2*h+1][0] = r1;                         \
                    b[2*h][1] = r2; b[2*h+1][1] = r3;                         \
                }                                                             \
            } else {                                                          \
                const float* bs =                                             \
                    BsBuf + (BUF) * BN * BK + (ks * 8 + bk) * BN;             \
                _Pragma("unroll")                                             \
                for (int nt = 0; nt < NT; nt++) {                             \
                    b[nt][0] = __float_as_uint(bs[bWord[nt]]);                \
                    b[nt][1] = __float_as_uint(bs[bWord[nt] + 4 * BN]);       \
                }                                                             \
            }                                                                 \
            _Pragma("unroll")                                                 \
            for (int mt = 0; mt < 4; mt++)                                    \
                _Pragma("unroll")                                             \
                for (int nt = 0; nt < NT; nt++)                               \
                    mma_tf32(acc[mt][nt], a[mt], b[nt]);                      \
        }                                                                     \
    }

    const int nIter = K >> 5;
    LDG_TILE(0);
    STS_TILE(0);
    __syncthreads();
    for (int it = 0; it < nIter; it++) {
        const int buf = it & 1;
        if (it + 1 < nIter) LDG_TILE(it + 1);
        COMPUTE(buf);
        if (it + 1 < nIter) STS_TILE(buf ^ 1);
        __syncthreads();
    }

#undef LDG_TILE
#undef STS_TILE
#undef COMPUTE

    // ---- epilogue ----
#pragma unroll
    for (int mt = 0; mt < 4; mt++) {
        const int r0 = m0 + wm * 64 + mt * 16 + (lane >> 2);
#pragma unroll
        for (int nt = 0; nt < NT; nt++) {
            const int c = n0 + wn * WNW + nt * 8 + ((lane & 3) << 1);
            float v0 = acc[mt][nt][0], v1 = acc[mt][nt][1];
            float v2 = acc[mt][nt][2], v3 = acc[mt][nt][3];
            if (mode == 1) {
                float b0 = bias[c], b1 = bias[c + 1];
                v0 += b0; v1 += b1; v2 += b0; v3 += b1;
            } else if (mode == 2) {
                float b0 = bias[c], b1 = bias[c + 1];
                v0 = gelu_f(v0 + b0); v1 = gelu_f(v1 + b1);
                v2 = gelu_f(v2 + b0); v3 = gelu_f(v3 + b1);
            } else if (mode == 3) {
                const size_t i0 = (size_t)r0 * ldc + c;
                const size_t i1 = (size_t)(r0 + 8) * ldc + c;
                v0 = v0 * scale + bias3[i0];
                v1 = v1 * scale + bias3[i0 + 1];
                v2 = v2 * scale + bias3[i1];
                v3 = v3 * scale + bias3[i1 + 1];
                if (mask[zb * SSZ + c] == 0)     { v0 = -9e15f; v2 = -9e15f; }
                if (mask[zb * SSZ + c + 1] == 0) { v1 = -9e15f; v3 = -9e15f; }
            }
            *(float2*)&C[(size_t)r0 * ldc + c]       = make_float2(v0, v1);
            *(float2*)&C[(size_t)(r0 + 8) * ldc + c] = make_float2(v2, v3);
        }
    }
}

// ---------------------------------------------------------------------------
// Row softmax, in-place, vectorized. One block per row, 256 threads.
// ---------------------------------------------------------------------------
__global__ void softmax_kernel(float* __restrict__ s) {
    __shared__ float sh[8];
    float4* p = (float4*)(s + (size_t)blockIdx.x * SSZ);
    int tid = threadIdx.x, lane = tid & 31, w = tid >> 5;

    float4 v = p[tid];
    float mx = fmaxf(fmaxf(v.x, v.y), fmaxf(v.z, v.w));
#pragma unroll
    for (int o = 16; o; o >>= 1) mx = fmaxf(mx, __shfl_xor_sync(0xffffffffu, mx, o));
    if (lane == 0) sh[w] = mx;
    __syncthreads();
    float m2 = (lane < 8) ? sh[lane] : -INFINITY;
#pragma unroll
    for (int o = 4; o; o >>= 1) m2 = fmaxf(m2, __shfl_xor_sync(0xffffffffu, m2, o));
    mx = __shfl_sync(0xffffffffu, m2, 0);

    v.x = __expf(v.x - mx); v.y = __expf(v.y - mx);
    v.z = __expf(v.z - mx); v.w = __expf(v.w - mx);
    float sum = v.x + v.y + v.z + v.w;
#pragma unroll
    for (int o = 16; o; o >>= 1) sum += __shfl_xor_sync(0xffffffffu, sum, o);
    __syncthreads();
    if (lane == 0) sh[w] = sum;
    __syncthreads();
    float s2 = (lane < 8) ? sh[lane] : 0.0f;
#pragma unroll
    for (int o = 4; o; o >>= 1) s2 += __shfl_xor_sync(0xffffffffu, s2, o);
    float inv = 1.0f / __shfl_sync(0xffffffffu, s2, 0);

    v.x *= inv; v.y *= inv; v.z *= inv; v.w *= inv;
    p[tid] = v;
}

// ---------------------------------------------------------------------------
// Fused residual add + LayerNorm, vectorized. One block per row, 256 threads.
// ---------------------------------------------------------------------------
__global__ void add_ln_kernel(const float* __restrict__ resid,
                              const float* __restrict__ add,
                              const float* __restrict__ g,
                              const float* __restrict__ bta,
                              float* __restrict__ out) {
    __shared__ float sh[8];
    const size_t base = (size_t)blockIdx.x * DSZ;
    int tid = threadIdx.x, lane = tid & 31, w = tid >> 5;

    float4 a = ((const float4*)(resid + base))[tid];
    float4 b = ((const float4*)(add + base))[tid];
    float4 v = make_float4(a.x + b.x, a.y + b.y, a.z + b.z, a.w + b.w);

    float sum = v.x + v.y + v.z + v.w;
#pragma unroll
    for (int o = 16; o; o >>= 1) sum += __shfl_xor_sync(0xffffffffu, sum, o);
    if (lane == 0) sh[w] = sum;
    __syncthreads();
    float t = (lane < 8) ? sh[lane] : 0.0f;
#pragma unroll
    for (int o = 4; o; o >>= 1) t += __shfl_xor_sync(0xffffffffu, t, o);
    float mu = __shfl_sync(0xffffffffu, t, 0) * (1.0f / DSZ);

    float dx = v.x - mu, dy = v.y - mu, dz = v.z - mu, dw = v.w - mu;
    float s2 = dx * dx + dy * dy + dz * dz + dw * dw;
#pragma unroll
    for (int o = 16; o; o >>= 1) s2 += __shfl_xor_sync(0xffffffffu, s2, o);
    __syncthreads();
    if (lane == 0) sh[w] = s2;
    __syncthreads();
    float t2 = (lane < 8) ? sh[lane] : 0.0f;
#pragma unroll
    for (int o = 4; o; o >>= 1) t2 += __shfl_xor_sync(0xffffffffu, t2, o);
    float rstd = rsqrtf(__shfl_sync(0xffffffffu, t2, 0) * (1.0f / DSZ) + 1e-6f);

    float4 gg = ((const float4*)g)[tid];
    float4 bb = ((const float4*)bta)[tid];
    float4 o4 = make_float4(dx * rstd * gg.x + bb.x, dy * rstd * gg.y + bb.y,
                            dz * rstd * gg.z + bb.z, dw * rstd * gg.w + bb.w);
    ((float4*)(out + base))[tid] = o4;
}

// ---------------------------------------------------------------------------
// Host-side orchestration
// ---------------------------------------------------------------------------
extern "C" void kernel_launch(void* const* d_in, const int* in_sizes, int n_in,
                              void* d_out, int out_size) {
    (void)in_sizes; (void)n_in; (void)out_size;

    const float* x_in  = (const float*)d_in[0];
    const int*   mask  = (const int*)  d_in[1];
    const float* bias  = (const float*)d_in[2];
    const float* Wq    = (const float*)d_in[3];
    const float* Wk    = (const float*)d_in[4];
    const float* Wv    = (const float*)d_in[5];
    const float* ln1g  = (const float*)d_in[6];
    const float* ln1b  = (const float*)d_in[7];
    const float* W1    = (const float*)d_in[8];
    const float* b1    = (const float*)d_in[9];
    const float* W2    = (const float*)d_in[10];
    const float* b2    = (const float*)d_in[11];
    const float* ln2g  = (const float*)d_in[12];
    const float* ln2b  = (const float*)d_in[13];
    float* out = (float*)d_out;

    float *q, *k, *v, *o, *x, *hbuf;
    cudaGetSymbolAddress((void**)&q, g_q);
    cudaGetSymbolAddress((void**)&k, g_k);
    cudaGetSymbolAddress((void**)&v, g_v);
    cudaGetSymbolAddress((void**)&o, g_o);
    cudaGetSymbolAddress((void**)&x, g_x);
    cudaGetSymbolAddress((void**)&hbuf, g_h);

    const int M = BSZ * SSZ;                               // 2048
    const long long SL = (long long)SSZ * SSZ;
    const long long SCORES_L = (long long)BSZ * HN * SL;
    const long long SD = (long long)SSZ * DSZ;

    const int SMEM_BIG  = (2 * 128 * 32 + 2 * 128 * 32) * 4;  // 65536
    const int SMEM_PV   = (2 * 128 * 32 + 2 * 64 * 32) * 4;   // 49152
    cudaFuncSetAttribute(mma_gemm<128, false>,
                         cudaFuncAttributeMaxDynamicSharedMemorySize, SMEM_BIG);
    cudaFuncSetAttribute(mma_gemm<128, true>,
                         cudaFuncAttributeMaxDynamicSharedMemorySize, SMEM_BIG);
    cudaFuncSetAttribute(mma_gemm<64, false>,
                         cudaFuncAttributeMaxDynamicSharedMemorySize, SMEM_PV);

    cudaMemcpyAsync(x, x_in, sizeof(float) * (size_t)M * DSZ, cudaMemcpyDeviceToDevice);

    dim3 thr(256);
    for (int n = 0; n < LN_LAYERS; n++) {
        const float* wq = Wq + (size_t)n * DSZ * DSZ;
        const float* wk = Wk + (size_t)n * DSZ * DSZ;
        const float* wv = Wv + (size_t)n * DSZ * DSZ;
        float* sl = out + (size_t)n * SCORES_L;

        // Fused QKV: z selects weight/output
        mma_gemm<128, false><<<dim3(DSZ / 128, M / 128, 3), thr, SMEM_BIG>>>(
            x, wq, wk, wv, q, k, v, DSZ, DSZ, DSZ, DSZ,
            0, 0, 0, 0, 0, 0, nullptr, nullptr, 0, 0.0f, 1);

        // Scores: per (b,h): Q_bh[S,64] @ K_bh[S,64]^T, fused scale+bias+mask
        mma_gemm<128, true><<<dim3(SSZ / 128, SSZ / 128, BSZ * HN), thr, SMEM_BIG>>>(
            q, k, k, k, sl, sl, sl, DSZ, DSZ, SSZ, DK,
            SD, (long long)DK, SD, (long long)DK,
            (long long)HN * SL, SL, bias, mask, 3, 0.125f, 0);

        softmax_kernel<<<BSZ * HN * SSZ, thr>>>(sl);

        // PV: per (b,h): [S,64] = P[S,S] @ V_bh[S,64]
        mma_gemm<64, false><<<dim3(1, SSZ / 128, BSZ * HN), thr, SMEM_PV>>>(
            sl, v, v, v, o, o, o, SSZ, DSZ, DSZ, SSZ,
            (long long)HN * SL, SL, SD, (long long)DK,
            SD, (long long)DK, nullptr, nullptr, 0, 0.0f, 0);

        add_ln_kernel<<<M, thr>>>(x, o, ln1g + n * DSZ, ln1b + n * DSZ, x);

        // FFN1 (+bias, gelu)
        mma_gemm<128, false><<<dim3(DFF / 128, M / 128, 1), thr, SMEM_BIG>>>(
            x, W1 + (size_t)n * DSZ * DFF, nullptr, nullptr, hbuf, nullptr, nullptr,
            DSZ, DFF, DFF, DSZ, 0, 0, 0, 0, 0, 0,
            b1 + (size_t)n * DFF, nullptr, 2, 0.0f, 0);
        // FFN2 (+bias)
        mma_gemm<128, false><<<dim3(DSZ / 128, M / 128, 1), thr, SMEM_BIG>>>(
            hbuf, W2 + (size_t)n * DFF * DSZ, nullptr, nullptr, o, nullptr, nullptr,
            DFF, DSZ, DSZ, DFF, 0, 0, 0, 0, 0, 0,
            b2 + (size_t)n * DSZ, nullptr, 1, 0.0f, 0);

        add_ln_kernel<<<M, thr>>>(x, o, ln2g + n * DSZ, ln2b + n * DSZ, x);
    }

    cudaMemcpyAsync(out + (size_t)LN_LAYERS * SCORES_L, x,
                    sizeof(float) * (size_t)M * DSZ, cudaMemcpyDeviceToDevice);
}